// round 15
// baseline (speedup 1.0000x reference)
#include <cuda_runtime.h>
#include <cuda_fp16.h>
#include <cstdint>

#define NROWS 32768
#define INDIM 128
#define DDIV  8
#define H1D   512
#define H2D   256
#define H3D   128
#define BN_EPS 1e-5f
#define NEG_SLOPE 0.01f
#define RBLOCKS  128          // route blocks (256 rows each)

// ---------------- scratch (static device globals; no allocation) -------------
__device__ __half g_xh[(size_t)NROWS * INDIM];        // fp16 x
__device__ __half g_h1[(size_t)NROWS * H1D];          // fp16 activations
__device__ __half g_h2[(size_t)NROWS * H2D];
__device__ __half g_wt1[(size_t)DDIV * H1D * INDIM];  // W^T [D][N][K] fp16
__device__ __half g_wt2[(size_t)DDIV * H2D * H1D];
__device__ __half g_wt3[(size_t)DDIV * H3D * H2D];
__device__ int    g_perm[NROWS];
__device__ int    g_rowBucket[NROWS];
__device__ int    g_blockCounts[RBLOCKS * DDIV];      // overwrite-only each run
__device__ int    g_counts[DDIV];
__device__ int    g_offsets[DDIV + 1];

// ---------------- PTX helpers (plain sm_80+ PTX) ------------------------------
__device__ __forceinline__ uint32_t smem_u32(const void* p) {
    uint32_t a;
    asm("{ .reg .u64 t; cvta.to.shared.u64 t, %1; cvt.u32.u64 %0, t; }" : "=r"(a) : "l"(p));
    return a;
}
__device__ __forceinline__ void cp16(uint32_t dst, const void* src) {
    asm volatile("cp.async.cg.shared.global [%0], [%1], 16;" :: "r"(dst), "l"(src));
}
__device__ __forceinline__ void cp_commit() {
    asm volatile("cp.async.commit_group;" ::: "memory");
}
__device__ __forceinline__ void cp_wait1() {
    asm volatile("cp.async.wait_group 1;" ::: "memory");
}
__device__ __forceinline__ void ldsm4(uint32_t& r0, uint32_t& r1, uint32_t& r2, uint32_t& r3,
                                      uint32_t addr) {
    asm volatile("ldmatrix.sync.aligned.m8n8.x4.shared.b16 {%0,%1,%2,%3}, [%4];"
                 : "=r"(r0), "=r"(r1), "=r"(r2), "=r"(r3) : "r"(addr));
}
__device__ __forceinline__ void mma_f16(float* c, uint32_t a0, uint32_t a1, uint32_t a2,
                                        uint32_t a3, uint32_t b0, uint32_t b1) {
    asm volatile(
        "mma.sync.aligned.m16n8k16.row.col.f32.f16.f16.f32 "
        "{%0,%1,%2,%3}, {%4,%5,%6,%7}, {%8,%9}, {%0,%1,%2,%3};"
        : "+f"(c[0]), "+f"(c[1]), "+f"(c[2]), "+f"(c[3])
        : "r"(a0), "r"(a1), "r"(a2), "r"(a3), "r"(b0), "r"(b1));
}

// ---------------- fused transpose (all 3 layers) -------------------------------
// W [D][K][N] fp32 -> Wt [D][N][K] fp16. Block = (32,8). (Identical to R6.)
__global__ void k_transpose_all(const float* __restrict__ W1,
                                const float* __restrict__ W2,
                                const float* __restrict__ W3)
{
    __shared__ float tile[32][33];
    int bid = blockIdx.x;
    int tx = threadIdx.x, ty = threadIdx.y;

    const float* in;
    __half* outp;
    int K, N, nt, kt, d;
    if (bid < 512) {               // L1
        K = INDIM; N = H1D; in = W1; outp = g_wt1;
        nt = bid & 15; kt = (bid >> 4) & 3; d = bid >> 6;
    } else if (bid < 1536) {       // L2
        int l = bid - 512;
        K = H1D; N = H2D; in = W2; outp = g_wt2;
        nt = l & 7; kt = (l >> 3) & 15; d = l >> 7;
    } else {                       // L3
        int l = bid - 1536;
        K = H2D; N = H3D; in = W3; outp = g_wt3;
        nt = l & 3; kt = (l >> 2) & 7; d = l >> 5;
    }
    int bx = nt * 32, by = kt * 32;
    const float* ip = in + (size_t)d * K * N;
    __half* op = outp + (size_t)d * N * K;
    #pragma unroll
    for (int i = 0; i < 32; i += 8)
        tile[ty + i][tx] = ip[(size_t)(by + ty + i) * N + bx + tx];
    __syncthreads();
    #pragma unroll
    for (int i = 0; i < 32; i += 8)
        op[(size_t)(bx + ty + i) * K + by + tx] = __float2half_rn(tile[tx][ty + i]);
}

// ---------------- route: 128 blocks x 256 rows, warp per row -------------------
// Writes fp16 x copy + per-block bucket counts (no global atomics).
__global__ void __launch_bounds__(256)
k_route(const float* __restrict__ x, float* __restrict__ out)
{
    __shared__ int scnt[DDIV];
    const int rbid    = blockIdx.x;
    const int rowBase = rbid * 256;
    const int tid  = threadIdx.x;
    const int wid  = tid >> 5;
    const int lane = tid & 31;
    if (tid < DDIV) scnt[tid] = 0;
    __syncthreads();

    #pragma unroll 4
    for (int p = 0; p < 32; p++) {
        int row = rowBase + p * 8 + wid;
        float4 v = *(const float4*)(x + (size_t)row * INDIM + lane * 4);
        __half2 h0 = __floats2half2_rn(v.x, v.y);
        __half2 h1 = __floats2half2_rn(v.z, v.w);
        *(__half2*)(g_xh + (size_t)row * INDIM + lane * 4)     = h0;
        *(__half2*)(g_xh + (size_t)row * INDIM + lane * 4 + 2) = h1;
        double s = (double)v.x + (double)v.y + (double)v.z + (double)v.w;
        #pragma unroll
        for (int o = 16; o > 0; o >>= 1)
            s += __shfl_down_sync(0xffffffffu, s, o);
        if (lane == 0) {
            out[row] = 0.0f;
            int bkt = (int)ceil(s * 0.0625) - 1;   // D/L = 8/128
            if (bkt >= 0 && bkt < DDIV) {
                g_rowBucket[row] = bkt;
                atomicAdd(&scnt[bkt], 1);
            } else {
                g_rowBucket[row] = -1;
            }
        }
    }
    __syncthreads();
    if (tid < DDIV) g_blockCounts[rbid * DDIV + tid] = scnt[tid];
}

// ---------------- assign (fused scan): 128 blocks, no global atomics ----------
// Each block redundantly reduces g_blockCounts to get bucket totals and its own
// exclusive per-bucket base; block 0 publishes counts/offsets for the GEMMs.
__global__ void __launch_bounds__(256)
k_assign2()
{
    __shared__ int scnt[DDIV];
    __shared__ int sbase[DDIV];
    __shared__ int tot[DDIV];
    const int rbid = blockIdx.x;
    const int tid  = threadIdx.x;

    if (tid < DDIV) {
        int t = 0, mb = 0;
        #pragma unroll 8
        for (int r = 0; r < RBLOCKS; r++) {
            int c = g_blockCounts[r * DDIV + tid];
            t += c;
            if (r < rbid) mb += c;
        }
        tot[tid]   = t;
        sbase[tid] = mb;
        scnt[tid]  = 0;
    }
    __syncthreads();
    if (tid == 0) {
        int acc = 0;
        #pragma unroll
        for (int b = 0; b < DDIV; b++) {
            sbase[b] += acc;
            if (rbid == 0) {
                g_offsets[b] = acc;
                g_counts[b]  = tot[b];
            }
            acc += tot[b];
        }
        if (rbid == 0) g_offsets[DDIV] = acc;
    }
    __syncthreads();

    int row = rbid * 256 + tid;
    int b = g_rowBucket[row];
    if (b >= 0) {
        int lp = atomicAdd(&scnt[b], 1);
        g_perm[sbase[b] + lp] = row;
    }
}

// ---------------- fp16 mma.sync GEMM + fused BN + leaky (exact R6) ------------
// CTA tile 128x128, BK=64 halves, 3-stage cp.async pipeline, 8 warps @ 64x32.
// XOR swizzle on 16B slots, 16KB/stage/operand, 2 CTAs/SM. Full grids
// dim3(tiles, colt, DDIV) with early exit. LAYER==3 fuses the W4 dot + scatter.
static constexpr int STG     = 16384;
static constexpr int NSTAGES = 3;
static constexpr int TAILB   = 4096;
static constexpr int GEMM_SMEM = 2 * NSTAGES * STG + TAILB;

template <int LAYER>
__global__ void __launch_bounds__(256, 2)
k_gemm_mma(const float* __restrict__ bl, const float* __restrict__ gg,
           const float* __restrict__ be, const float* __restrict__ mm,
           const float* __restrict__ vv,
           const float* __restrict__ W4, const float* __restrict__ b4,
           float* __restrict__ finalOut)
{
    constexpr int K    = (LAYER == 1) ? INDIM : (LAYER == 2) ? H1D : H2D;
    constexpr int NOUT = (LAYER == 1) ? H1D  : (LAYER == 2) ? H2D : H3D;
    constexpr int NCH  = K / 64;

    const __half* A  = (LAYER == 1) ? g_xh : (LAYER == 2) ? g_h1 : g_h2;
    const __half* Wt = (LAYER == 1) ? g_wt1 : (LAYER == 2) ? g_wt2 : g_wt3;
    __half* Out      = (LAYER == 1) ? g_h1 : g_h2;   // unused for LAYER==3

    const int bD    = blockIdx.z;
    const int cnt   = g_counts[bD];
    const int tile0 = blockIdx.x * 128;
    if (tile0 >= cnt) return;
    const int base    = g_offsets[bD] + tile0;
    const int mrows   = min(128, cnt - tile0);
    const int colBase = blockIdx.y * 128;

    extern __shared__ char smem[];
    const uint32_t sb = smem_u32(smem);
    float* scp  = (float*)(smem + 2 * NSTAGES * STG);
    float* bsp  = scp + 128;
    float* w4s  = scp + 256;   // LAYER==3 only
    float* rowp = scp + 384;   // LAYER==3 only: [128][4]

    const int tid  = threadIdx.x;
    const int lane = tid & 31;
    const int warp = tid >> 5;
    const int m0   = (warp >> 2) * 64;
    const int n0   = (warp & 3) * 32;

    if (tid < 128) {
        int c = colBase + tid;
        size_t idx = (size_t)bD * NOUT + c;
        float s = gg[idx] * rsqrtf(vv[idx] + BN_EPS);
        scp[tid] = s;
        bsp[tid] = (bl[idx] - mm[idx]) * s + be[idx];
        if (LAYER == 3) w4s[tid] = W4[(size_t)bD * H3D + tid];
    }

    // cp.async source pointers + swizzled smem offsets
    const __half* aRow[4];
    const __half* bRow[4];
    uint32_t smOff[4];
    const int rBase = tid >> 3;
    const int c4    = tid & 7;
    const uint32_t c4x = (uint32_t)((c4 ^ (rBase & 7)) << 4);
    #pragma unroll
    for (int i = 0; i < 4; i++) {
        int r  = rBase + 32 * i;
        int rc = min(r, mrows - 1);
        if (LAYER == 1) aRow[i] = A + (size_t)g_perm[base + rc] * K;
        else            aRow[i] = A + (size_t)(base + rc) * K;
        bRow[i] = Wt + ((size_t)bD * NOUT + colBase + r) * K;
        smOff[i] = (uint32_t)(r * 128) + c4x;
    }

    // pipeline prologue: stages 0,1 (NCH >= 2 always)
    #pragma unroll
    for (int p = 0; p < 2; p++) {
        int k0 = p * 64 + c4 * 8;
        uint32_t as = sb + p * STG, bs = sb + (NSTAGES + p) * STG;
        #pragma unroll
        for (int i = 0; i < 4; i++) cp16(as + smOff[i], aRow[i] + k0);
        #pragma unroll
        for (int i = 0; i < 4; i++) cp16(bs + smOff[i], bRow[i] + k0);
        cp_commit();
    }

    // ldmatrix addressing
    const int sel = lane >> 4;
    const int x7  = lane & 7;
    uint32_t colX[4];
    #pragma unroll
    for (int kk = 0; kk < 4; kk++)
        colX[kk] = (uint32_t)(((kk * 2 + sel) ^ x7) << 4);
    const uint32_t aRowOff = (uint32_t)((m0 + (lane & 15)) * 128);
    const uint32_t bRowOff = (uint32_t)((n0 + (lane & 15)) * 128);

    float acc[4][4][4];
    #pragma unroll
    for (int i = 0; i < 4; i++)
        #pragma unroll
        for (int j = 0; j < 4; j++)
            #pragma unroll
            for (int q = 0; q < 4; q++) acc[i][j][q] = 0.0f;

    for (int c = 0; c < NCH; c++) {
        cp_wait1();
        __syncthreads();

        if (c + 2 < NCH) {
            int slot = (c + 2) % NSTAGES;
            int k0 = (c + 2) * 64 + c4 * 8;
            uint32_t as = sb + slot * STG, bs = sb + (NSTAGES + slot) * STG;
            #pragma unroll
            for (int i = 0; i < 4; i++) cp16(as + smOff[i], aRow[i] + k0);
            #pragma unroll
            for (int i = 0; i < 4; i++) cp16(bs + smOff[i], bRow[i] + k0);
        }
        cp_commit();

        int s = c % NSTAGES;
        uint32_t aB = sb + s * STG + aRowOff;
        uint32_t bB = sb + (NSTAGES + s) * STG + bRowOff;
        #pragma unroll
        for (int kk = 0; kk < 4; kk++) {
            uint32_t af[4][4], bf[2][4];
            #pragma unroll
            for (int mt = 0; mt < 4; mt++)
                ldsm4(af[mt][0], af[mt][1], af[mt][2], af[mt][3],
                      aB + mt * 2048 + colX[kk]);
            #pragma unroll
            for (int np = 0; np < 2; np++)
                ldsm4(bf[np][0], bf[np][1], bf[np][2], bf[np][3],
                      bB + np * 2048 + colX[kk]);
            #pragma unroll
            for (int mt = 0; mt < 4; mt++)
                #pragma unroll
                for (int nt = 0; nt < 4; nt++)
                    mma_f16(acc[mt][nt], af[mt][0], af[mt][1], af[mt][2], af[mt][3],
                            bf[nt >> 1][nt & 1], bf[nt >> 1][(nt & 1) + 2]);
        }
    }

    // ---------------- epilogue ----------------
    const int g  = lane >> 2;
    const int tg = lane & 3;

    if (LAYER < 3) {
        #pragma unroll
        for (int mt = 0; mt < 4; mt++) {
            int r0 = m0 + mt * 16 + g;
            int r1 = r0 + 8;
            __half* o0 = Out + (size_t)(base + r0) * NOUT + colBase;
            __half* o1 = Out + (size_t)(base + r1) * NOUT + colBase;
            #pragma unroll
            for (int nt = 0; nt < 4; nt++) {
                int col = n0 + nt * 8 + tg * 2;
                float s0 = scp[col], s1 = scp[col + 1];
                float t0 = bsp[col], t1 = bsp[col + 1];
                float y00 = acc[mt][nt][0] * s0 + t0;
                float y01 = acc[mt][nt][1] * s1 + t1;
                float y10 = acc[mt][nt][2] * s0 + t0;
                float y11 = acc[mt][nt][3] * s1 + t1;
                y00 = (y00 >= 0.f) ? y00 : NEG_SLOPE * y00;
                y01 = (y01 >= 0.f) ? y01 : NEG_SLOPE * y01;
                y10 = (y10 >= 0.f) ? y10 : NEG_SLOPE * y10;
                y11 = (y11 >= 0.f) ? y11 : NEG_SLOPE * y11;
                if (r0 < mrows) *(__half2*)(o0 + col) = __floats2half2_rn(y00, y01);
                if (r1 < mrows) *(__half2*)(o1 + col) = __floats2half2_rn(y10, y11);
            }
        }
    } else {
        // fused final dot: out[row] = sum_c leaky(bn(h3))[c] * W4[c] + b4
        __syncthreads();   // scp/bsp/w4s final; reuse barrier before rowp writes
        #pragma unroll
        for (int mt = 0; mt < 4; mt++) {
            float p0 = 0.f, p1 = 0.f;
            #pragma unroll
            for (int nt = 0; nt < 4; nt++) {
                int col = n0 + nt * 8 + tg * 2;
                float s0 = scp[col], s1 = scp[col + 1];
                float t0 = bsp[col], t1 = bsp[col + 1];
                float y00 = acc[mt][nt][0] * s0 + t0;
                float y01 = acc[mt][nt][1] * s1 + t1;
                float y10 = acc[mt][nt][2] * s0 + t0;
                float y11 = acc[mt][nt][3] * s1 + t1;
                y00 = (y00 >= 0.f) ? y00 : NEG_SLOPE * y00;
                y01 = (y01 >= 0.f) ? y01 : NEG_SLOPE * y01;
                y10 = (y10 >= 0.f) ? y10 : NEG_SLOPE * y10;
                y11 = (y11 >= 0.f) ? y11 : NEG_SLOPE * y11;
                p0 += y00 * w4s[col] + y01 * w4s[col + 1];
                p1 += y10 * w4s[col] + y11 * w4s[col + 1];
            }
            p0 += __shfl_xor_sync(0xffffffffu, p0, 1);
            p0 += __shfl_xor_sync(0xffffffffu, p0, 2);
            p1 += __shfl_xor_sync(0xffffffffu, p1, 1);
            p1 += __shfl_xor_sync(0xffffffffu, p1, 2);
            if (tg == 0) {
                rowp[(m0 + mt * 16 + g) * 4 + (warp & 3)] = p0;
                rowp[(m0 + mt * 16 + g + 8) * 4 + (warp & 3)] = p1;
            }
        }
        __syncthreads();
        if (tid < 128 && tid < mrows) {
            float s = rowp[tid * 4] + rowp[tid * 4 + 1] +
                      rowp[tid * 4 + 2] + rowp[tid * 4 + 3] + b4[bD];
            finalOut[g_perm[base + tid]] = s;
        }
    }
}

// ---------------- launch ------------------------------------------------------
extern "C" void kernel_launch(void* const* d_in, const int* in_sizes, int n_in,
                              void* d_out, int out_size)
{
    const float* x   = (const float*)d_in[0];
    const float* W1  = (const float*)d_in[1];
    const float* b1  = (const float*)d_in[2];
    const float* g1  = (const float*)d_in[3];
    const float* be1 = (const float*)d_in[4];
    const float* m1  = (const float*)d_in[5];
    const float* v1  = (const float*)d_in[6];
    const float* W2  = (const float*)d_in[7];
    const float* b2  = (const float*)d_in[8];
    const float* g2  = (const float*)d_in[9];
    const float* be2 = (const float*)d_in[10];
    const float* m2  = (const float*)d_in[11];
    const float* v2  = (const float*)d_in[12];
    const float* W3  = (const float*)d_in[13];
    const float* b3  = (const float*)d_in[14];
    const float* g3  = (const float*)d_in[15];
    const float* be3 = (const float*)d_in[16];
    const float* m3  = (const float*)d_in[17];
    const float* v3  = (const float*)d_in[18];
    const float* W4  = (const float*)d_in[19];
    const float* b4  = (const float*)d_in[20];
    float* out = (float*)d_out;

    cudaFuncSetAttribute(k_gemm_mma<1>, cudaFuncAttributeMaxDynamicSharedMemorySize, GEMM_SMEM);
    cudaFuncSetAttribute(k_gemm_mma<2>, cudaFuncAttributeMaxDynamicSharedMemorySize, GEMM_SMEM);
    cudaFuncSetAttribute(k_gemm_mma<3>, cudaFuncAttributeMaxDynamicSharedMemorySize, GEMM_SMEM);

    k_transpose_all<<<1792, dim3(32, 8)>>>(W1, W2, W3);
    k_route<<<RBLOCKS, 256>>>(x, out);
    k_assign2<<<RBLOCKS, 256>>>();

    k_gemm_mma<1><<<dim3(NROWS / 128, H1D / 128, DDIV), 256, GEMM_SMEM>>>(
        b1, g1, be1, m1, v1, nullptr, nullptr, nullptr);
    k_gemm_mma<2><<<dim3(NROWS / 128, H2D / 128, DDIV), 256, GEMM_SMEM>>>(
        b2, g2, be2, m2, v2, nullptr, nullptr, nullptr);
    k_gemm_mma<3><<<dim3(NROWS / 128, 1, DDIV), 256, GEMM_SMEM>>>(
        b3, g3, be3, m3, v3, W4, b4, out);
}

// round 16
// speedup vs baseline: 1.1425x; 1.1425x over previous
#include <cuda_runtime.h>
#include <cuda_fp16.h>
#include <cstdint>

#define NROWS 32768
#define INDIM 128
#define DDIV  8
#define H1D   512
#define H2D   256
#define H3D   128
#define BN_EPS 1e-5f
#define NEG_SLOPE 0.01f

// ---------------- scratch (static device globals; no allocation) -------------
__device__ __half g_xh[(size_t)NROWS * INDIM];        // fp16 x
__device__ __half g_h1[(size_t)NROWS * H1D];          // fp16 activations
__device__ __half g_h2[(size_t)NROWS * H2D];
__device__ __half g_wt1[(size_t)DDIV * H1D * INDIM];  // W^T [D][N][K] fp16
__device__ __half g_wt2[(size_t)DDIV * H2D * H1D];
__device__ __half g_wt3[(size_t)DDIV * H3D * H2D];
__device__ int    g_perm[NROWS];
__device__ int    g_rowBucket[NROWS];
__device__ int    g_counts[DDIV];
__device__ int    g_offsets[DDIV + 1];
__device__ int    g_cursor[DDIV];

// ---------------- PTX helpers (plain sm_80+ PTX) ------------------------------
__device__ __forceinline__ uint32_t smem_u32(const void* p) {
    uint32_t a;
    asm("{ .reg .u64 t; cvta.to.shared.u64 t, %1; cvt.u32.u64 %0, t; }" : "=r"(a) : "l"(p));
    return a;
}
__device__ __forceinline__ void cp16(uint32_t dst, const void* src) {
    asm volatile("cp.async.cg.shared.global [%0], [%1], 16;" :: "r"(dst), "l"(src));
}
__device__ __forceinline__ void cp_commit() {
    asm volatile("cp.async.commit_group;" ::: "memory");
}
__device__ __forceinline__ void cp_wait1() {
    asm volatile("cp.async.wait_group 1;" ::: "memory");
}
__device__ __forceinline__ void ldsm4(uint32_t& r0, uint32_t& r1, uint32_t& r2, uint32_t& r3,
                                      uint32_t addr) {
    asm volatile("ldmatrix.sync.aligned.m8n8.x4.shared.b16 {%0,%1,%2,%3}, [%4];"
                 : "=r"(r0), "=r"(r1), "=r"(r2), "=r"(r3) : "r"(addr));
}
__device__ __forceinline__ void mma_f16(float* c, uint32_t a0, uint32_t a1, uint32_t a2,
                                        uint32_t a3, uint32_t b0, uint32_t b1) {
    asm volatile(
        "mma.sync.aligned.m16n8k16.row.col.f32.f16.f16.f32 "
        "{%0,%1,%2,%3}, {%4,%5,%6,%7}, {%8,%9}, {%0,%1,%2,%3};"
        : "+f"(c[0]), "+f"(c[1]), "+f"(c[2]), "+f"(c[3])
        : "r"(a0), "r"(a1), "r"(a2), "r"(a3), "r"(b0), "r"(b1));
}

// ---------------- fused transpose (all 3 layers) + zero counts ----------------
// W [D][K][N] fp32 -> Wt [D][N][K] fp16. Block = (32,8).
__global__ void k_transpose_all(const float* __restrict__ W1,
                                const float* __restrict__ W2,
                                const float* __restrict__ W3)
{
    __shared__ float tile[32][33];
    int bid = blockIdx.x;
    int tx = threadIdx.x, ty = threadIdx.y;

    if (bid == 0 && ty == 0 && tx < DDIV) g_counts[tx] = 0;

    const float* in;
    __half* outp;
    int K, N, nt, kt, d;
    if (bid < 512) {               // L1
        K = INDIM; N = H1D; in = W1; outp = g_wt1;
        nt = bid & 15; kt = (bid >> 4) & 3; d = bid >> 6;
    } else if (bid < 1536) {       // L2
        int l = bid - 512;
        K = H1D; N = H2D; in = W2; outp = g_wt2;
        nt = l & 7; kt = (l >> 3) & 15; d = l >> 7;
    } else {                       // L3
        int l = bid - 1536;
        K = H2D; N = H3D; in = W3; outp = g_wt3;
        nt = l & 3; kt = (l >> 2) & 7; d = l >> 5;
    }
    int bx = nt * 32, by = kt * 32;
    const float* ip = in + (size_t)d * K * N;
    __half* op = outp + (size_t)d * N * K;
    #pragma unroll
    for (int i = 0; i < 32; i += 8)
        tile[ty + i][tx] = ip[(size_t)(by + ty + i) * N + bx + tx];
    __syncthreads();
    #pragma unroll
    for (int i = 0; i < 32; i += 8)
        op[(size_t)(bx + ty + i) * K + by + tx] = __float2half_rn(tile[tx][ty + i]);
}

// ---------------- routing -----------------------------------------------------
__global__ void k_route(const float* __restrict__ x, float* __restrict__ out) {
    __shared__ int scnt[DDIV];
    int t = threadIdx.x;
    if (t < DDIV) scnt[t] = 0;
    __syncthreads();
    int row  = blockIdx.x * 32 + (t >> 5);
    int lane = t & 31;
    float4 v = *(const float4*)(x + (size_t)row * INDIM + lane * 4);
    __half2 h0 = __floats2half2_rn(v.x, v.y);
    __half2 h1 = __floats2half2_rn(v.z, v.w);
    *(__half2*)(g_xh + (size_t)row * INDIM + lane * 4)     = h0;
    *(__half2*)(g_xh + (size_t)row * INDIM + lane * 4 + 2) = h1;
    double s = (double)v.x + (double)v.y + (double)v.z + (double)v.w;
    #pragma unroll
    for (int o = 16; o > 0; o >>= 1)
        s += __shfl_down_sync(0xffffffffu, s, o);
    if (lane == 0) {
        out[row] = 0.0f;
        int bkt = (int)ceil(s * 0.0625) - 1;   // D/L = 8/128
        if (bkt >= 0 && bkt < DDIV) {
            g_rowBucket[row] = bkt;
            atomicAdd(&scnt[bkt], 1);
        } else {
            g_rowBucket[row] = -1;
        }
    }
    __syncthreads();
    if (t < DDIV && scnt[t] > 0) atomicAdd(&g_counts[t], scnt[t]);
}

__global__ void k_scan() {
    if (threadIdx.x == 0) {
        int acc = 0;
        #pragma unroll
        for (int i = 0; i < DDIV; i++) {
            g_offsets[i] = acc;
            g_cursor[i]  = acc;
            acc += g_counts[i];
        }
        g_offsets[DDIV] = acc;
    }
}

__global__ void k_assign() {
    __shared__ int scnt[DDIV];
    __shared__ int sbase[DDIV];
    int t = threadIdx.x;
    if (t < DDIV) scnt[t] = 0;
    __syncthreads();
    int row = blockIdx.x * 256 + t;
    int b = g_rowBucket[row];
    int lp = 0;
    if (b >= 0) lp = atomicAdd(&scnt[b], 1);
    __syncthreads();
    if (t < DDIV && scnt[t] > 0) sbase[t] = atomicAdd(&g_cursor[t], scnt[t]);
    __syncthreads();
    if (b >= 0) g_perm[sbase[b] + lp] = row;
}

// ---------------- fp16 mma.sync GEMM + fused BN + leaky ----------------------
// CTA tile 128x128, BK=64 halves (128B rows), 3-stage cp.async pipeline,
// 8 warps @ 64x32. XOR swizzle on 16B slots. 16KB/stage/operand.
// LAYER==3 additionally fuses the final W4 dot + scatter to d_out.
static constexpr int STG     = 16384;
static constexpr int NSTAGES = 3;
static constexpr int TAILB   = 4096;
static constexpr int GEMM_SMEM = 2 * NSTAGES * STG + TAILB;

template <int LAYER>
__global__ void __launch_bounds__(256, 2)
k_gemm_mma(const float* __restrict__ bl, const float* __restrict__ gg,
           const float* __restrict__ be, const float* __restrict__ mm,
           const float* __restrict__ vv,
           const float* __restrict__ W4, const float* __restrict__ b4,
           float* __restrict__ finalOut)
{
    constexpr int K    = (LAYER == 1) ? INDIM : (LAYER == 2) ? H1D : H2D;
    constexpr int NOUT = (LAYER == 1) ? H1D  : (LAYER == 2) ? H2D : H3D;
    constexpr int NCH  = K / 64;

    const __half* A  = (LAYER == 1) ? g_xh : (LAYER == 2) ? g_h1 : g_h2;
    const __half* Wt = (LAYER == 1) ? g_wt1 : (LAYER == 2) ? g_wt2 : g_wt3;
    __half* Out      = (LAYER == 1) ? g_h1 : g_h2;   // unused for LAYER==3

    const int bD    = blockIdx.z;
    const int cnt   = g_counts[bD];
    const int tile0 = blockIdx.x * 128;
    if (tile0 >= cnt) return;
    const int base    = g_offsets[bD] + tile0;
    const int mrows   = min(128, cnt - tile0);
    const int colBase = blockIdx.y * 128;

    extern __shared__ char smem[];
    const uint32_t sb = smem_u32(smem);
    float* scp  = (float*)(smem + 2 * NSTAGES * STG);
    float* bsp  = scp + 128;
    float* w4s  = scp + 256;   // LAYER==3 only
    float* rowp = scp + 384;   // LAYER==3 only: [128][4]

    const int tid  = threadIdx.x;
    const int lane = tid & 31;
    const int warp = tid >> 5;
    const int m0   = (warp >> 2) * 64;
    const int n0   = (warp & 3) * 32;

    if (tid < 128) {
        int c = colBase + tid;
        size_t idx = (size_t)bD * NOUT + c;
        float s = gg[idx] * rsqrtf(vv[idx] + BN_EPS);
        scp[tid] = s;
        bsp[tid] = (bl[idx] - mm[idx]) * s + be[idx];
        if (LAYER == 3) w4s[tid] = W4[(size_t)bD * H3D + tid];
    }

    // cp.async source pointers + swizzled smem offsets
    const __half* aRow[4];
    const __half* bRow[4];
    uint32_t smOff[4];
    const int rBase = tid >> 3;
    const int c4    = tid & 7;
    const uint32_t c4x = (uint32_t)((c4 ^ (rBase & 7)) << 4);
    #pragma unroll
    for (int i = 0; i < 4; i++) {
        int r  = rBase + 32 * i;
        int rc = min(r, mrows - 1);
        if (LAYER == 1) aRow[i] = A + (size_t)g_perm[base + rc] * K;
        else            aRow[i] = A + (size_t)(base + rc) * K;
        bRow[i] = Wt + ((size_t)bD * NOUT + colBase + r) * K;
        smOff[i] = (uint32_t)(r * 128) + c4x;
    }

    // pipeline prologue: stages 0,1 (NCH >= 2 always)
    #pragma unroll
    for (int p = 0; p < 2; p++) {
        int k0 = p * 64 + c4 * 8;
        uint32_t as = sb + p * STG, bs = sb + (NSTAGES + p) * STG;
        #pragma unroll
        for (int i = 0; i < 4; i++) cp16(as + smOff[i], aRow[i] + k0);
        #pragma unroll
        for (int i = 0; i < 4; i++) cp16(bs + smOff[i], bRow[i] + k0);
        cp_commit();
    }

    // ldmatrix addressing: rows = base + (lane&15), 16B slot = (kk*2+sel)^ (lane&7)
    const int sel = lane >> 4;
    const int x7  = lane & 7;
    uint32_t colX[4];
    #pragma unroll
    for (int kk = 0; kk < 4; kk++)
        colX[kk] = (uint32_t)(((kk * 2 + sel) ^ x7) << 4);
    const uint32_t aRowOff = (uint32_t)((m0 + (lane & 15)) * 128);
    const uint32_t bRowOff = (uint32_t)((n0 + (lane & 15)) * 128);

    float acc[4][4][4];
    #pragma unroll
    for (int i = 0; i < 4; i++)
        #pragma unroll
        for (int j = 0; j < 4; j++)
            #pragma unroll
            for (int q = 0; q < 4; q++) acc[i][j][q] = 0.0f;

    for (int c = 0; c < NCH; c++) {
        cp_wait1();
        __syncthreads();

        if (c + 2 < NCH) {
            int slot = (c + 2) % NSTAGES;
            int k0 = (c + 2) * 64 + c4 * 8;
            uint32_t as = sb + slot * STG, bs = sb + (NSTAGES + slot) * STG;
            #pragma unroll
            for (int i = 0; i < 4; i++) cp16(as + smOff[i], aRow[i] + k0);
            #pragma unroll
            for (int i = 0; i < 4; i++) cp16(bs + smOff[i], bRow[i] + k0);
        }
        cp_commit();

        int s = c % NSTAGES;
        uint32_t aB = sb + s * STG + aRowOff;
        uint32_t bB = sb + (NSTAGES + s) * STG + bRowOff;
        #pragma unroll
        for (int kk = 0; kk < 4; kk++) {
            uint32_t af[4][4], bf[2][4];
            #pragma unroll
            for (int mt = 0; mt < 4; mt++)
                ldsm4(af[mt][0], af[mt][1], af[mt][2], af[mt][3],
                      aB + mt * 2048 + colX[kk]);
            #pragma unroll
            for (int np = 0; np < 2; np++)
                ldsm4(bf[np][0], bf[np][1], bf[np][2], bf[np][3],
                      bB + np * 2048 + colX[kk]);
            #pragma unroll
            for (int mt = 0; mt < 4; mt++)
                #pragma unroll
                for (int nt = 0; nt < 4; nt++)
                    mma_f16(acc[mt][nt], af[mt][0], af[mt][1], af[mt][2], af[mt][3],
                            bf[nt >> 1][nt & 1], bf[nt >> 1][(nt & 1) + 2]);
        }
    }

    // ---------------- epilogue ----------------
    const int g  = lane >> 2;
    const int tg = lane & 3;

    if (LAYER < 3) {
        #pragma unroll
        for (int mt = 0; mt < 4; mt++) {
            int r0 = m0 + mt * 16 + g;
            int r1 = r0 + 8;
            __half* o0 = Out + (size_t)(base + r0) * NOUT + colBase;
            __half* o1 = Out + (size_t)(base + r1) * NOUT + colBase;
            #pragma unroll
            for (int nt = 0; nt < 4; nt++) {
                int col = n0 + nt * 8 + tg * 2;
                float s0 = scp[col], s1 = scp[col + 1];
                float t0 = bsp[col], t1 = bsp[col + 1];
                float y00 = acc[mt][nt][0] * s0 + t0;
                float y01 = acc[mt][nt][1] * s1 + t1;
                float y10 = acc[mt][nt][2] * s0 + t0;
                float y11 = acc[mt][nt][3] * s1 + t1;
                y00 = (y00 >= 0.f) ? y00 : NEG_SLOPE * y00;
                y01 = (y01 >= 0.f) ? y01 : NEG_SLOPE * y01;
                y10 = (y10 >= 0.f) ? y10 : NEG_SLOPE * y10;
                y11 = (y11 >= 0.f) ? y11 : NEG_SLOPE * y11;
                if (r0 < mrows) *(__half2*)(o0 + col) = __floats2half2_rn(y00, y01);
                if (r1 < mrows) *(__half2*)(o1 + col) = __floats2half2_rn(y10, y11);
            }
        }
    } else {
        // fused final dot: out[row] = sum_c leaky(bn(h3))[c] * W4[c] + b4
        __syncthreads();   // scp/bsp/w4s final; reuse barrier before rowp writes
        #pragma unroll
        for (int mt = 0; mt < 4; mt++) {
            float p0 = 0.f, p1 = 0.f;
            #pragma unroll
            for (int nt = 0; nt < 4; nt++) {
                int col = n0 + nt * 8 + tg * 2;
                float s0 = scp[col], s1 = scp[col + 1];
                float t0 = bsp[col], t1 = bsp[col + 1];
                float y00 = acc[mt][nt][0] * s0 + t0;
                float y01 = acc[mt][nt][1] * s1 + t1;
                float y10 = acc[mt][nt][2] * s0 + t0;
                float y11 = acc[mt][nt][3] * s1 + t1;
                y00 = (y00 >= 0.f) ? y00 : NEG_SLOPE * y00;
                y01 = (y01 >= 0.f) ? y01 : NEG_SLOPE * y01;
                y10 = (y10 >= 0.f) ? y10 : NEG_SLOPE * y10;
                y11 = (y11 >= 0.f) ? y11 : NEG_SLOPE * y11;
                p0 += y00 * w4s[col] + y01 * w4s[col + 1];
                p1 += y10 * w4s[col] + y11 * w4s[col + 1];
            }
            p0 += __shfl_xor_sync(0xffffffffu, p0, 1);
            p0 += __shfl_xor_sync(0xffffffffu, p0, 2);
            p1 += __shfl_xor_sync(0xffffffffu, p1, 1);
            p1 += __shfl_xor_sync(0xffffffffu, p1, 2);
            if (tg == 0) {
                rowp[(m0 + mt * 16 + g) * 4 + (warp & 3)] = p0;
                rowp[(m0 + mt * 16 + g + 8) * 4 + (warp & 3)] = p1;
            }
        }
        __syncthreads();
        if (tid < 128 && tid < mrows) {
            float s = rowp[tid * 4] + rowp[tid * 4 + 1] +
                      rowp[tid * 4 + 2] + rowp[tid * 4 + 3] + b4[bD];
            finalOut[g_perm[base + tid]] = s;
        }
    }
}

// ---------------- launch ------------------------------------------------------
extern "C" void kernel_launch(void* const* d_in, const int* in_sizes, int n_in,
                              void* d_out, int out_size)
{
    const float* x   = (const float*)d_in[0];
    const float* W1  = (const float*)d_in[1];
    const float* b1  = (const float*)d_in[2];
    const float* g1  = (const float*)d_in[3];
    const float* be1 = (const float*)d_in[4];
    const float* m1  = (const float*)d_in[5];
    const float* v1  = (const float*)d_in[6];
    const float* W2  = (const float*)d_in[7];
    const float* b2  = (const float*)d_in[8];
    const float* g2  = (const float*)d_in[9];
    const float* be2 = (const float*)d_in[10];
    const float* m2  = (const float*)d_in[11];
    const float* v2  = (const float*)d_in[12];
    const float* W3  = (const float*)d_in[13];
    const float* b3  = (const float*)d_in[14];
    const float* g3  = (const float*)d_in[15];
    const float* be3 = (const float*)d_in[16];
    const float* m3  = (const float*)d_in[17];
    const float* v3  = (const float*)d_in[18];
    const float* W4  = (const float*)d_in[19];
    const float* b4  = (const float*)d_in[20];
    float* out = (float*)d_out;

    cudaFuncSetAttribute(k_gemm_mma<1>, cudaFuncAttributeMaxDynamicSharedMemorySize, GEMM_SMEM);
    cudaFuncSetAttribute(k_gemm_mma<2>, cudaFuncAttributeMaxDynamicSharedMemorySize, GEMM_SMEM);
    cudaFuncSetAttribute(k_gemm_mma<3>, cudaFuncAttributeMaxDynamicSharedMemorySize, GEMM_SMEM);

    k_transpose_all<<<1792, dim3(32, 8)>>>(W1, W2, W3);   // also zeroes g_counts
    k_route<<<NROWS / 32, 1024>>>(x, out);
    k_scan<<<1, 32>>>();
    k_assign<<<NROWS / 256, 256>>>();

    k_gemm_mma<1><<<dim3(NROWS / 128, H1D / 128, DDIV), 256, GEMM_SMEM>>>(
        b1, g1, be1, m1, v1, nullptr, nullptr, nullptr);
    k_gemm_mma<2><<<dim3(NROWS / 128, H2D / 128, DDIV), 256, GEMM_SMEM>>>(
        b2, g2, be2, m2, v2, nullptr, nullptr, nullptr);
    k_gemm_mma<3><<<dim3(NROWS / 128, 1, DDIV), 256, GEMM_SMEM>>>(
        b3, g3, be3, m3, v3, W4, b4, out);
}

// round 17
// speedup vs baseline: 1.1915x; 1.0429x over previous
#include <cuda_runtime.h>
#include <cuda_fp16.h>
#include <cstdint>

#define NROWS 32768
#define INDIM 128
#define DDIV  8
#define H1D   512
#define H2D   256
#define H3D   128
#define BN_EPS 1e-5f
#define NEG_SLOPE 0.01f
#define ROUTEB   1024         // route blocks (32 rows each, 8 warps x 4 iters)
#define TBLOCKS  1792         // transpose blocks (after route in k_pre)

// ---------------- scratch (static device globals; no allocation) -------------
__device__ __half g_xh[(size_t)NROWS * INDIM];        // fp16 x
__device__ __half g_h1[(size_t)NROWS * H1D];          // fp16 activations
__device__ __half g_h2[(size_t)NROWS * H2D];
__device__ __half g_wt1[(size_t)DDIV * H1D * INDIM];  // W^T [D][N][K] fp16
__device__ __half g_wt2[(size_t)DDIV * H2D * H1D];
__device__ __half g_wt3[(size_t)DDIV * H3D * H2D];
__device__ int    g_perm[NROWS];
__device__ int    g_rowBucket[NROWS];
__device__ int    g_blockCounts[ROUTEB * DDIV];       // overwrite-only each run
__device__ int    g_counts[DDIV];
__device__ int    g_offsets[DDIV + 1];
__device__ int    g_cursor[DDIV];

// ---------------- PTX helpers (plain sm_80+ PTX) ------------------------------
__device__ __forceinline__ uint32_t smem_u32(const void* p) {
    uint32_t a;
    asm("{ .reg .u64 t; cvta.to.shared.u64 t, %1; cvt.u32.u64 %0, t; }" : "=r"(a) : "l"(p));
    return a;
}
__device__ __forceinline__ void cp16(uint32_t dst, const void* src) {
    asm volatile("cp.async.cg.shared.global [%0], [%1], 16;" :: "r"(dst), "l"(src));
}
__device__ __forceinline__ void cp_commit() {
    asm volatile("cp.async.commit_group;" ::: "memory");
}
__device__ __forceinline__ void cp_wait1() {
    asm volatile("cp.async.wait_group 1;" ::: "memory");
}
__device__ __forceinline__ void ldsm4(uint32_t& r0, uint32_t& r1, uint32_t& r2, uint32_t& r3,
                                      uint32_t addr) {
    asm volatile("ldmatrix.sync.aligned.m8n8.x4.shared.b16 {%0,%1,%2,%3}, [%4];"
                 : "=r"(r0), "=r"(r1), "=r"(r2), "=r"(r3) : "r"(addr));
}
__device__ __forceinline__ void mma_f16(float* c, uint32_t a0, uint32_t a1, uint32_t a2,
                                        uint32_t a3, uint32_t b0, uint32_t b1) {
    asm volatile(
        "mma.sync.aligned.m16n8k16.row.col.f32.f16.f16.f32 "
        "{%0,%1,%2,%3}, {%4,%5,%6,%7}, {%8,%9}, {%0,%1,%2,%3};"
        : "+f"(c[0]), "+f"(c[1]), "+f"(c[2]), "+f"(c[3])
        : "r"(a0), "r"(a1), "r"(a2), "r"(a3), "r"(b0), "r"(b1));
}

// ---------------- preamble: route (0..1023, WIDE) then transpose --------------
__global__ void __launch_bounds__(256)
k_pre(const float* __restrict__ x,
      const float* __restrict__ W1, const float* __restrict__ W2,
      const float* __restrict__ W3, float* __restrict__ out)
{
    const int bid = blockIdx.x;
    const int tid = threadIdx.x;

    if (bid < ROUTEB) {
        // ---- route: 32 rows per block; warp w handles rows it*8+w (4 iters) --
        __shared__ int scnt[DDIV];
        const int wid  = tid >> 5;
        const int lane = tid & 31;
        if (tid < DDIV) {
            scnt[tid] = 0;
            if (bid == 0) g_cursor[tid] = 0;   // only k_assign uses cursor: safe
        }
        __syncthreads();

        #pragma unroll
        for (int it = 0; it < 4; it++) {
            int row = bid * 32 + it * 8 + wid;
            float4 v = *(const float4*)(x + (size_t)row * INDIM + lane * 4);
            __half2 h0 = __floats2half2_rn(v.x, v.y);
            __half2 h1 = __floats2half2_rn(v.z, v.w);
            *(__half2*)(g_xh + (size_t)row * INDIM + lane * 4)     = h0;
            *(__half2*)(g_xh + (size_t)row * INDIM + lane * 4 + 2) = h1;
            double s = (double)v.x + (double)v.y + (double)v.z + (double)v.w;
            #pragma unroll
            for (int o = 16; o > 0; o >>= 1)
                s += __shfl_down_sync(0xffffffffu, s, o);
            if (lane == 0) {
                out[row] = 0.0f;
                int bkt = (int)ceil(s * 0.0625) - 1;   // D/L = 8/128
                if (bkt >= 0 && bkt < DDIV) {
                    g_rowBucket[row] = bkt;
                    atomicAdd(&scnt[bkt], 1);
                } else {
                    g_rowBucket[row] = -1;
                }
            }
        }
        __syncthreads();
        if (tid < DDIV) g_blockCounts[bid * DDIV + tid] = scnt[tid];
        return;
    }

    // ---- weight transpose fp32 -> fp16, [D][K][N] -> [D][N][K] ----
    const int tb = bid - ROUTEB;
    __shared__ float tile[32][33];
    int tx = tid & 31, ty = tid >> 5;
    const float* in;
    __half* outp;
    int K, N, nt, kt, d;
    if (tb < 512) {                // L1
        K = INDIM; N = H1D; in = W1; outp = g_wt1;
        nt = tb & 15; kt = (tb >> 4) & 3; d = tb >> 6;
    } else if (tb < 1536) {        // L2
        int l = tb - 512;
        K = H1D; N = H2D; in = W2; outp = g_wt2;
        nt = l & 7; kt = (l >> 3) & 15; d = l >> 7;
    } else {                       // L3
        int l = tb - 1536;
        K = H2D; N = H3D; in = W3; outp = g_wt3;
        nt = l & 3; kt = (l >> 2) & 7; d = l >> 5;
    }
    int bx = nt * 32, by = kt * 32;
    const float* ip = in + (size_t)d * K * N;
    __half* op = outp + (size_t)d * N * K;
    #pragma unroll
    for (int i = 0; i < 32; i += 8)
        tile[ty + i][tx] = ip[(size_t)(by + ty + i) * N + bx + tx];
    __syncthreads();
    #pragma unroll
    for (int i = 0; i < 32; i += 8)
        op[(size_t)(bx + ty + i) * K + by + tx] = __float2half_rn(tile[tx][ty + i]);
}

// ---------------- assign (fused scan): 128 blocks ------------------------------
// Each block reduces g_blockCounts (1024x8) for bucket totals, computes offsets
// locally, and claims its write range via g_cursor (zeroed in k_pre). Block 0
// publishes g_counts / g_offsets for the GEMM kernels.
__global__ void __launch_bounds__(256)
k_assign()
{
    __shared__ int psum[32][DDIV];
    __shared__ int soff[DDIV];
    __shared__ int scnt[DDIV];
    __shared__ int sbase[DDIV];
    __shared__ int tot[DDIV];
    const int tid = threadIdx.x;

    // reduce 1024x8 table: thread (ch, b) sums 32 rows
    {
        int b = tid & 7, ch = tid >> 3;   // 32 chunks x 8 buckets
        int acc = 0;
        #pragma unroll 8
        for (int r = 0; r < 32; r++)
            acc += g_blockCounts[(ch * 32 + r) * DDIV + b];
        psum[ch][b] = acc;
    }
    __syncthreads();
    if (tid < DDIV) {
        int t = 0;
        #pragma unroll
        for (int c = 0; c < 32; c++) t += psum[c][tid];
        tot[tid]  = t;
        scnt[tid] = 0;
    }
    __syncthreads();
    if (tid == 0) {
        int acc = 0;
        #pragma unroll
        for (int b = 0; b < DDIV; b++) {
            soff[b] = acc;
            if (blockIdx.x == 0) {
                g_offsets[b] = acc;
                g_counts[b]  = tot[b];
            }
            acc += tot[b];
        }
        if (blockIdx.x == 0) g_offsets[DDIV] = acc;
    }
    __syncthreads();

    int row = blockIdx.x * 256 + tid;
    int b = g_rowBucket[row];
    int lp = 0;
    if (b >= 0) lp = atomicAdd(&scnt[b], 1);
    __syncthreads();
    if (tid < DDIV && scnt[tid] > 0)
        sbase[tid] = soff[tid] + atomicAdd(&g_cursor[tid], scnt[tid]);
    __syncthreads();
    if (b >= 0) g_perm[sbase[b] + lp] = row;
}

// ---------------- fp16 mma.sync GEMM + fused BN + leaky (exact R6/R16) --------
static constexpr int STG     = 16384;
static constexpr int NSTAGES = 3;
static constexpr int TAILB   = 4096;
static constexpr int GEMM_SMEM = 2 * NSTAGES * STG + TAILB;

template <int LAYER>
__global__ void __launch_bounds__(256, 2)
k_gemm_mma(const float* __restrict__ bl, const float* __restrict__ gg,
           const float* __restrict__ be, const float* __restrict__ mm,
           const float* __restrict__ vv,
           const float* __restrict__ W4, const float* __restrict__ b4,
           float* __restrict__ finalOut)
{
    constexpr int K    = (LAYER == 1) ? INDIM : (LAYER == 2) ? H1D : H2D;
    constexpr int NOUT = (LAYER == 1) ? H1D  : (LAYER == 2) ? H2D : H3D;
    constexpr int NCH  = K / 64;

    const __half* A  = (LAYER == 1) ? g_xh : (LAYER == 2) ? g_h1 : g_h2;
    const __half* Wt = (LAYER == 1) ? g_wt1 : (LAYER == 2) ? g_wt2 : g_wt3;
    __half* Out      = (LAYER == 1) ? g_h1 : g_h2;   // unused for LAYER==3

    const int bD    = blockIdx.z;
    const int cnt   = g_counts[bD];
    const int tile0 = blockIdx.x * 128;
    if (tile0 >= cnt) return;
    const int base    = g_offsets[bD] + tile0;
    const int mrows   = min(128, cnt - tile0);
    const int colBase = blockIdx.y * 128;

    extern __shared__ char smem[];
    const uint32_t sb = smem_u32(smem);
    float* scp  = (float*)(smem + 2 * NSTAGES * STG);
    float* bsp  = scp + 128;
    float* w4s  = scp + 256;   // LAYER==3 only
    float* rowp = scp + 384;   // LAYER==3 only: [128][4]

    const int tid  = threadIdx.x;
    const int lane = tid & 31;
    const int warp = tid >> 5;
    const int m0   = (warp >> 2) * 64;
    const int n0   = (warp & 3) * 32;

    if (tid < 128) {
        int c = colBase + tid;
        size_t idx = (size_t)bD * NOUT + c;
        float s = gg[idx] * rsqrtf(vv[idx] + BN_EPS);
        scp[tid] = s;
        bsp[tid] = (bl[idx] - mm[idx]) * s + be[idx];
        if (LAYER == 3) w4s[tid] = W4[(size_t)bD * H3D + tid];
    }

    const __half* aRow[4];
    const __half* bRow[4];
    uint32_t smOff[4];
    const int rBase = tid >> 3;
    const int c4    = tid & 7;
    const uint32_t c4x = (uint32_t)((c4 ^ (rBase & 7)) << 4);
    #pragma unroll
    for (int i = 0; i < 4; i++) {
        int r  = rBase + 32 * i;
        int rc = min(r, mrows - 1);
        if (LAYER == 1) aRow[i] = A + (size_t)g_perm[base + rc] * K;
        else            aRow[i] = A + (size_t)(base + rc) * K;
        bRow[i] = Wt + ((size_t)bD * NOUT + colBase + r) * K;
        smOff[i] = (uint32_t)(r * 128) + c4x;
    }

    #pragma unroll
    for (int p = 0; p < 2; p++) {
        int k0 = p * 64 + c4 * 8;
        uint32_t as = sb + p * STG, bs = sb + (NSTAGES + p) * STG;
        #pragma unroll
        for (int i = 0; i < 4; i++) cp16(as + smOff[i], aRow[i] + k0);
        #pragma unroll
        for (int i = 0; i < 4; i++) cp16(bs + smOff[i], bRow[i] + k0);
        cp_commit();
    }

    const int sel = lane >> 4;
    const int x7  = lane & 7;
    uint32_t colX[4];
    #pragma unroll
    for (int kk = 0; kk < 4; kk++)
        colX[kk] = (uint32_t)(((kk * 2 + sel) ^ x7) << 4);
    const uint32_t aRowOff = (uint32_t)((m0 + (lane & 15)) * 128);
    const uint32_t bRowOff = (uint32_t)((n0 + (lane & 15)) * 128);

    float acc[4][4][4];
    #pragma unroll
    for (int i = 0; i < 4; i++)
        #pragma unroll
        for (int j = 0; j < 4; j++)
            #pragma unroll
            for (int q = 0; q < 4; q++) acc[i][j][q] = 0.0f;

    for (int c = 0; c < NCH; c++) {
        cp_wait1();
        __syncthreads();

        if (c + 2 < NCH) {
            int slot = (c + 2) % NSTAGES;
            int k0 = (c + 2) * 64 + c4 * 8;
            uint32_t as = sb + slot * STG, bs = sb + (NSTAGES + slot) * STG;
            #pragma unroll
            for (int i = 0; i < 4; i++) cp16(as + smOff[i], aRow[i] + k0);
            #pragma unroll
            for (int i = 0; i < 4; i++) cp16(bs + smOff[i], bRow[i] + k0);
        }
        cp_commit();

        int s = c % NSTAGES;
        uint32_t aB = sb + s * STG + aRowOff;
        uint32_t bB = sb + (NSTAGES + s) * STG + bRowOff;
        #pragma unroll
        for (int kk = 0; kk < 4; kk++) {
            uint32_t af[4][4], bf[2][4];
            #pragma unroll
            for (int mt = 0; mt < 4; mt++)
                ldsm4(af[mt][0], af[mt][1], af[mt][2], af[mt][3],
                      aB + mt * 2048 + colX[kk]);
            #pragma unroll
            for (int np = 0; np < 2; np++)
                ldsm4(bf[np][0], bf[np][1], bf[np][2], bf[np][3],
                      bB + np * 2048 + colX[kk]);
            #pragma unroll
            for (int mt = 0; mt < 4; mt++)
                #pragma unroll
                for (int nt = 0; nt < 4; nt++)
                    mma_f16(acc[mt][nt], af[mt][0], af[mt][1], af[mt][2], af[mt][3],
                            bf[nt >> 1][nt & 1], bf[nt >> 1][(nt & 1) + 2]);
        }
    }

    const int g  = lane >> 2;
    const int tg = lane & 3;

    if (LAYER < 3) {
        #pragma unroll
        for (int mt = 0; mt < 4; mt++) {
            int r0 = m0 + mt * 16 + g;
            int r1 = r0 + 8;
            __half* o0 = Out + (size_t)(base + r0) * NOUT + colBase;
            __half* o1 = Out + (size_t)(base + r1) * NOUT + colBase;
            #pragma unroll
            for (int nt = 0; nt < 4; nt++) {
                int col = n0 + nt * 8 + tg * 2;
                float s0 = scp[col], s1 = scp[col + 1];
                float t0 = bsp[col], t1 = bsp[col + 1];
                float y00 = acc[mt][nt][0] * s0 + t0;
                float y01 = acc[mt][nt][1] * s1 + t1;
                float y10 = acc[mt][nt][2] * s0 + t0;
                float y11 = acc[mt][nt][3] * s1 + t1;
                y00 = (y00 >= 0.f) ? y00 : NEG_SLOPE * y00;
                y01 = (y01 >= 0.f) ? y01 : NEG_SLOPE * y01;
                y10 = (y10 >= 0.f) ? y10 : NEG_SLOPE * y10;
                y11 = (y11 >= 0.f) ? y11 : NEG_SLOPE * y11;
                if (r0 < mrows) *(__half2*)(o0 + col) = __floats2half2_rn(y00, y01);
                if (r1 < mrows) *(__half2*)(o1 + col) = __floats2half2_rn(y10, y11);
            }
        }
    } else {
        // fused final dot: out[row] = sum_c leaky(bn(h3))[c] * W4[c] + b4
        __syncthreads();
        #pragma unroll
        for (int mt = 0; mt < 4; mt++) {
            float p0 = 0.f, p1 = 0.f;
            #pragma unroll
            for (int nt = 0; nt < 4; nt++) {
                int col = n0 + nt * 8 + tg * 2;
                float s0 = scp[col], s1 = scp[col + 1];
                float t0 = bsp[col], t1 = bsp[col + 1];
                float y00 = acc[mt][nt][0] * s0 + t0;
                float y01 = acc[mt][nt][1] * s1 + t1;
                float y10 = acc[mt][nt][2] * s0 + t0;
                float y11 = acc[mt][nt][3] * s1 + t1;
                y00 = (y00 >= 0.f) ? y00 : NEG_SLOPE * y00;
                y01 = (y01 >= 0.f) ? y01 : NEG_SLOPE * y01;
                y10 = (y10 >= 0.f) ? y10 : NEG_SLOPE * y10;
                y11 = (y11 >= 0.f) ? y11 : NEG_SLOPE * y11;
                p0 += y00 * w4s[col] + y01 * w4s[col + 1];
                p1 += y10 * w4s[col] + y11 * w4s[col + 1];
            }
            p0 += __shfl_xor_sync(0xffffffffu, p0, 1);
            p0 += __shfl_xor_sync(0xffffffffu, p0, 2);
            p1 += __shfl_xor_sync(0xffffffffu, p1, 1);
            p1 += __shfl_xor_sync(0xffffffffu, p1, 2);
            if (tg == 0) {
                rowp[(m0 + mt * 16 + g) * 4 + (warp & 3)] = p0;
                rowp[(m0 + mt * 16 + g + 8) * 4 + (warp & 3)] = p1;
            }
        }
        __syncthreads();
        if (tid < 128 && tid < mrows) {
            float s = rowp[tid * 4] + rowp[tid * 4 + 1] +
                      rowp[tid * 4 + 2] + rowp[tid * 4 + 3] + b4[bD];
            finalOut[g_perm[base + tid]] = s;
        }
    }
}

// ---------------- launch ------------------------------------------------------
extern "C" void kernel_launch(void* const* d_in, const int* in_sizes, int n_in,
                              void* d_out, int out_size)
{
    const float* x   = (const float*)d_in[0];
    const float* W1  = (const float*)d_in[1];
    const float* b1  = (const float*)d_in[2];
    const float* g1  = (const float*)d_in[3];
    const float* be1 = (const float*)d_in[4];
    const float* m1  = (const float*)d_in[5];
    const float* v1  = (const float*)d_in[6];
    const float* W2  = (const float*)d_in[7];
    const float* b2  = (const float*)d_in[8];
    const float* g2  = (const float*)d_in[9];
    const float* be2 = (const float*)d_in[10];
    const float* m2  = (const float*)d_in[11];
    const float* v2  = (const float*)d_in[12];
    const float* W3  = (const float*)d_in[13];
    const float* b3  = (const float*)d_in[14];
    const float* g3  = (const float*)d_in[15];
    const float* be3 = (const float*)d_in[16];
    const float* m3  = (const float*)d_in[17];
    const float* v3  = (const float*)d_in[18];
    const float* W4  = (const float*)d_in[19];
    const float* b4  = (const float*)d_in[20];
    float* out = (float*)d_out;

    cudaFuncSetAttribute(k_gemm_mma<1>, cudaFuncAttributeMaxDynamicSharedMemorySize, GEMM_SMEM);
    cudaFuncSetAttribute(k_gemm_mma<2>, cudaFuncAttributeMaxDynamicSharedMemorySize, GEMM_SMEM);
    cudaFuncSetAttribute(k_gemm_mma<3>, cudaFuncAttributeMaxDynamicSharedMemorySize, GEMM_SMEM);

    k_pre<<<ROUTEB + TBLOCKS, 256>>>(x, W1, W2, W3, out);
    k_assign<<<NROWS / 256, 256>>>();

    k_gemm_mma<1><<<dim3(NROWS / 128, H1D / 128, DDIV), 256, GEMM_SMEM>>>(
        b1, g1, be1, m1, v1, nullptr, nullptr, nullptr);
    k_gemm_mma<2><<<dim3(NROWS / 128, H2D / 128, DDIV), 256, GEMM_SMEM>>>(
        b2, g2, be2, m2, v2, nullptr, nullptr, nullptr);
    k_gemm_mma<3><<<dim3(NROWS / 128, 1, DDIV), 256, GEMM_SMEM>>>(
        b3, g3, be3, m3, v3, W4, b4, out);
}